// round 1
// baseline (speedup 1.0000x reference)
#include <cuda_runtime.h>
#include <math_constants.h>

// ---------------------------------------------------------------------------
// SparseEventNet: segment mean+max pool (N rows, C=128, sorted batch ids)
// followed by a tiny MLP head (2C -> 128 -> 64 -> 32 -> 4).
// HBM-bound: 1.024 GB feature stream read exactly once.
// ---------------------------------------------------------------------------

#define C_CH 128
#define B_MAX 1024

// Scratch (no cudaMalloc allowed): per-segment accumulators.
__device__ float    g_sum[B_MAX * C_CH];
__device__ unsigned g_maxk[B_MAX * C_CH];
__device__ float    g_cnt[B_MAX];

// Monotonic float<->uint mapping so atomicMax(unsigned) == float max.
__device__ __forceinline__ unsigned f2k(float f) {
    unsigned b = __float_as_uint(f);
    return (b & 0x80000000u) ? ~b : (b | 0x80000000u);
}
__device__ __forceinline__ float k2f(unsigned k) {
    unsigned b = (k & 0x80000000u) ? (k & 0x7FFFFFFFu) : ~k;
    return __uint_as_float(b);
}
// f2k(-inf) = ~0xFF800000 = 0x007FFFFF
#define NEG_INF_KEY 0x007FFFFFu

__global__ void init_kernel(int B) {
    int i = blockIdx.x * blockDim.x + threadIdx.x;
    if (i < B * C_CH) {
        g_sum[i]  = 0.0f;
        g_maxk[i] = NEG_INF_KEY;
    }
    if (i < B) g_cnt[i] = 0.0f;
}

// ---------------------------------------------------------------------------
// Segment reduce: one warp owns a contiguous row range. Lane l holds channels
// [4l, 4l+4) in registers (float4). Flush to global atomics only on segment
// change / range end.
// ---------------------------------------------------------------------------
__global__ void __launch_bounds__(256) reduce_kernel(
    const float4* __restrict__ feat,   // [N, 32] float4 view of [N, 128]
    const int*    __restrict__ bids,   // [N], sorted
    int N, int rows_per_warp)
{
    const int gw   = (blockIdx.x * blockDim.x + threadIdx.x) >> 5;
    const int lane = threadIdx.x & 31;

    int r    = gw * rows_per_warp;
    if (r >= N) return;
    int rend = min(N, r + rows_per_warp);

    int    cur = bids[r];
    float4 s   = make_float4(0.f, 0.f, 0.f, 0.f);
    float4 m   = make_float4(-CUDART_INF_F, -CUDART_INF_F, -CUDART_INF_F, -CUDART_INF_F);
    int    cnt = 0;

#define ACC(v)                                         \
    do {                                               \
        s.x += (v).x; s.y += (v).y;                    \
        s.z += (v).z; s.w += (v).w;                    \
        m.x = fmaxf(m.x, (v).x); m.y = fmaxf(m.y, (v).y); \
        m.z = fmaxf(m.z, (v).z); m.w = fmaxf(m.w, (v).w); \
    } while (0)

#define FLUSH()                                                              \
    do {                                                                     \
        if (cnt > 0) {                                                       \
            float*    sp = &g_sum [cur * C_CH + lane * 4];                   \
            unsigned* mp = &g_maxk[cur * C_CH + lane * 4];                   \
            atomicAdd(sp + 0, s.x); atomicAdd(sp + 1, s.y);                  \
            atomicAdd(sp + 2, s.z); atomicAdd(sp + 3, s.w);                  \
            atomicMax(mp + 0, f2k(m.x)); atomicMax(mp + 1, f2k(m.y));        \
            atomicMax(mp + 2, f2k(m.z)); atomicMax(mp + 3, f2k(m.w));        \
            if (lane == 0) atomicAdd(&g_cnt[cur], (float)cnt);               \
        }                                                                    \
    } while (0)

#define STEP(b, v)                                                           \
    do {                                                                     \
        if ((b) != cur) {                                                    \
            FLUSH();                                                         \
            cur = (b);                                                       \
            s = make_float4(0.f, 0.f, 0.f, 0.f);                             \
            m = make_float4(-CUDART_INF_F, -CUDART_INF_F,                    \
                            -CUDART_INF_F, -CUDART_INF_F);                   \
            cnt = 0;                                                         \
        }                                                                    \
        ACC(v);                                                              \
        cnt++;                                                               \
    } while (0)

    // 4-row unrolled main loop: front-batched loads for MLP.
    while (r + 4 <= rend) {
        int a0 = bids[r + 0];
        int a1 = bids[r + 1];
        int a2 = bids[r + 2];
        int a3 = bids[r + 3];
        float4 v0 = feat[(r + 0) * 32 + lane];
        float4 v1 = feat[(r + 1) * 32 + lane];
        float4 v2 = feat[(r + 2) * 32 + lane];
        float4 v3 = feat[(r + 3) * 32 + lane];
        if (a0 == cur && a3 == cur) {
            // sorted ids: a1,a2 == cur too. Fast path, no boundary checks.
            ACC(v0); ACC(v1); ACC(v2); ACC(v3);
            cnt += 4;
        } else {
            STEP(a0, v0); STEP(a1, v1); STEP(a2, v2); STEP(a3, v3);
        }
        r += 4;
    }
    while (r < rend) {
        int    a = bids[r];
        float4 v = feat[r * 32 + lane];
        STEP(a, v);
        r++;
    }
    FLUSH();

#undef STEP
#undef FLUSH
#undef ACC
}

// ---------------------------------------------------------------------------
// Finalize pooling + MLP head. One block (128 threads) per batch element.
// pooled = [mean(128) | max(128)]; empty segments -> zeros.
// ---------------------------------------------------------------------------
__global__ void __launch_bounds__(128) head_kernel(
    const float* __restrict__ W1, const float* __restrict__ b1,   // [256,128],[128]
    const float* __restrict__ W2, const float* __restrict__ b2,   // [128, 64],[ 64]
    const float* __restrict__ W3, const float* __restrict__ b3,   // [ 64, 32],[ 32]
    const float* __restrict__ W4, const float* __restrict__ b4,   // [ 32,  4],[  4]
    float* __restrict__ out)                                      // [B, 4]
{
    const int b = blockIdx.x;
    const int t = threadIdx.x;

    __shared__ float pooled[2 * C_CH];
    __shared__ float h1[128];
    __shared__ float h2[64];
    __shared__ float h3[32];

    float cnt = g_cnt[b];
    bool  ne  = cnt > 0.0f;
    float sum = g_sum[b * C_CH + t];
    float mx  = k2f(g_maxk[b * C_CH + t]);
    pooled[t]        = ne ? (sum / cnt) : 0.0f;
    pooled[C_CH + t] = ne ? mx : 0.0f;
    __syncthreads();

    // Layer 1: [256] -> [128]
    {
        float acc = b1[t];
#pragma unroll 8
        for (int i = 0; i < 2 * C_CH; i++) acc += pooled[i] * W1[i * 128 + t];
        h1[t] = fmaxf(acc, 0.0f);
    }
    __syncthreads();

    // Layer 2: [128] -> [64]
    if (t < 64) {
        float acc = b2[t];
#pragma unroll 8
        for (int i = 0; i < 128; i++) acc += h1[i] * W2[i * 64 + t];
        h2[t] = fmaxf(acc, 0.0f);
    }
    __syncthreads();

    // Layer 3: [64] -> [32]
    if (t < 32) {
        float acc = b3[t];
#pragma unroll 8
        for (int i = 0; i < 64; i++) acc += h2[i] * W3[i * 32 + t];
        h3[t] = fmaxf(acc, 0.0f);
    }
    __syncthreads();

    // Layer 4: [32] -> [4]
    if (t < 4) {
        float acc = b4[t];
#pragma unroll
        for (int i = 0; i < 32; i++) acc += h3[i] * W4[i * 4 + t];
        out[b * 4 + t] = acc;
    }
}

// ---------------------------------------------------------------------------
extern "C" void kernel_launch(void* const* d_in, const int* in_sizes, int n_in,
                              void* d_out, int out_size)
{
    const float* feat = (const float*)d_in[0];
    const int*   bids = (const int*)d_in[1];

    // Inputs (metadata order): features, batch_ids, [batch_size scalar?],
    // W1,b1,W2,b2,W3,b3,W4,b4. Detect whether the scalar batch_size is present.
    int wbase = 2;
    if (n_in >= 11 && in_sizes[2] == 1) wbase = 3;  // skip scalar batch_size

    const float* W1 = (const float*)d_in[wbase + 0];
    const float* b1 = (const float*)d_in[wbase + 1];
    const float* W2 = (const float*)d_in[wbase + 2];
    const float* b2 = (const float*)d_in[wbase + 3];
    const float* W3 = (const float*)d_in[wbase + 4];
    const float* b3 = (const float*)d_in[wbase + 5];
    const float* W4 = (const float*)d_in[wbase + 6];
    const float* b4 = (const float*)d_in[wbase + 7];

    const int N = in_sizes[0] / C_CH;     // rows
    const int B = out_size / 4;           // batch size from output shape

    // 1) init scratch
    {
        int total   = B * C_CH;
        int threads = 256;
        int blocks  = (total + threads - 1) / threads;
        init_kernel<<<blocks, threads>>>(B);
    }

    // 2) segment reduce: 148 SMs * 8 blocks * 8 warps = 9472 warps
    {
        int blocks  = 1184;
        int threads = 256;
        int total_warps = blocks * (threads / 32);
        int rpw = (N + total_warps - 1) / total_warps;
        reduce_kernel<<<blocks, threads>>>((const float4*)feat, bids, N, rpw);
    }

    // 3) finalize + MLP head
    head_kernel<<<B, 128>>>(W1, b1, W2, b2, W3, b3, W4, b4, (float*)d_out);
}

// round 2
// speedup vs baseline: 1.1062x; 1.1062x over previous
#include <cuda_runtime.h>
#include <math_constants.h>

// ---------------------------------------------------------------------------
// SparseEventNet: segment mean+max pool (N rows, C=128, sorted batch ids)
// followed by a tiny MLP head (2C -> 128 -> 64 -> 32 -> 4).
// HBM-bound: 1.024 GB feature stream read exactly once.
// R2: 8-row unroll (MLP=8), streaming loads, endpoint-only bids fast path.
// ---------------------------------------------------------------------------

#define C_CH 128
#define B_MAX 1024

// Scratch (no cudaMalloc allowed): per-segment accumulators.
__device__ float    g_sum[B_MAX * C_CH];
__device__ unsigned g_maxk[B_MAX * C_CH];
__device__ float    g_cnt[B_MAX];

// Monotonic float<->uint mapping so atomicMax(unsigned) == float max.
__device__ __forceinline__ unsigned f2k(float f) {
    unsigned b = __float_as_uint(f);
    return (b & 0x80000000u) ? ~b : (b | 0x80000000u);
}
__device__ __forceinline__ float k2f(unsigned k) {
    unsigned b = (k & 0x80000000u) ? (k & 0x7FFFFFFFu) : ~k;
    return __uint_as_float(b);
}
// f2k(-inf) = ~0xFF800000 = 0x007FFFFF
#define NEG_INF_KEY 0x007FFFFFu

__global__ void init_kernel(int B) {
    int i = blockIdx.x * blockDim.x + threadIdx.x;
    if (i < B * C_CH) {
        g_sum[i]  = 0.0f;
        g_maxk[i] = NEG_INF_KEY;
    }
    if (i < B) g_cnt[i] = 0.0f;
}

// ---------------------------------------------------------------------------
// Segment reduce: one warp owns a contiguous row range. Lane l holds channels
// [4l, 4l+4) in registers (float4). Flush to global atomics only on segment
// change / range end. 8-row unroll, endpoint bids check (ids are sorted).
// ---------------------------------------------------------------------------
__global__ void __launch_bounds__(256) reduce_kernel(
    const float4* __restrict__ feat,   // [N, 32] float4 view of [N, 128]
    const int*    __restrict__ bids,   // [N], sorted
    int N, int rows_per_warp)
{
    const int gw   = (blockIdx.x * blockDim.x + threadIdx.x) >> 5;
    const int lane = threadIdx.x & 31;

    int r    = gw * rows_per_warp;
    if (r >= N) return;
    int rend = min(N, r + rows_per_warp);

    int    cur = bids[r];
    float4 s   = make_float4(0.f, 0.f, 0.f, 0.f);
    float4 m   = make_float4(-CUDART_INF_F, -CUDART_INF_F, -CUDART_INF_F, -CUDART_INF_F);
    int    cnt = 0;

#define ACC(v)                                                \
    do {                                                      \
        s.x += (v).x; s.y += (v).y;                           \
        s.z += (v).z; s.w += (v).w;                           \
        m.x = fmaxf(m.x, (v).x); m.y = fmaxf(m.y, (v).y);     \
        m.z = fmaxf(m.z, (v).z); m.w = fmaxf(m.w, (v).w);     \
    } while (0)

#define FLUSH()                                                              \
    do {                                                                     \
        if (cnt > 0) {                                                       \
            float*    sp = &g_sum [cur * C_CH + lane * 4];                   \
            unsigned* mp = &g_maxk[cur * C_CH + lane * 4];                   \
            atomicAdd(sp + 0, s.x); atomicAdd(sp + 1, s.y);                  \
            atomicAdd(sp + 2, s.z); atomicAdd(sp + 3, s.w);                  \
            atomicMax(mp + 0, f2k(m.x)); atomicMax(mp + 1, f2k(m.y));        \
            atomicMax(mp + 2, f2k(m.z)); atomicMax(mp + 3, f2k(m.w));        \
            if (lane == 0) atomicAdd(&g_cnt[cur], (float)cnt);               \
        }                                                                    \
    } while (0)

#define STEP(b, v)                                                           \
    do {                                                                     \
        if ((b) != cur) {                                                    \
            FLUSH();                                                         \
            cur = (b);                                                       \
            s = make_float4(0.f, 0.f, 0.f, 0.f);                             \
            m = make_float4(-CUDART_INF_F, -CUDART_INF_F,                    \
                            -CUDART_INF_F, -CUDART_INF_F);                   \
            cnt = 0;                                                         \
        }                                                                    \
        ACC(v);                                                              \
        cnt++;                                                               \
    } while (0)

    // 8-row unrolled main loop: 8 front-batched streaming LDG.128 per thread.
    while (r + 8 <= rend) {
        // sorted ids: if both endpoints match cur, all 8 rows are interior.
        int b0 = bids[r];
        int b7 = bids[r + 7];
        const float4* p = feat + (size_t)r * 32 + lane;
        float4 v0 = __ldcs(p +   0);
        float4 v1 = __ldcs(p +  32);
        float4 v2 = __ldcs(p +  64);
        float4 v3 = __ldcs(p +  96);
        float4 v4 = __ldcs(p + 128);
        float4 v5 = __ldcs(p + 160);
        float4 v6 = __ldcs(p + 192);
        float4 v7 = __ldcs(p + 224);
        if (b0 == cur && b7 == cur) {
            ACC(v0); ACC(v1); ACC(v2); ACC(v3);
            ACC(v4); ACC(v5); ACC(v6); ACC(v7);
            cnt += 8;
        } else {
            int a1 = bids[r + 1], a2 = bids[r + 2], a3 = bids[r + 3];
            int a4 = bids[r + 4], a5 = bids[r + 5], a6 = bids[r + 6];
            STEP(b0, v0); STEP(a1, v1); STEP(a2, v2); STEP(a3, v3);
            STEP(a4, v4); STEP(a5, v5); STEP(a6, v6); STEP(b7, v7);
        }
        r += 8;
    }
    while (r < rend) {
        int    a = bids[r];
        float4 v = __ldcs(feat + (size_t)r * 32 + lane);
        STEP(a, v);
        r++;
    }
    FLUSH();

#undef STEP
#undef FLUSH
#undef ACC
}

// ---------------------------------------------------------------------------
// Finalize pooling + MLP head. One block (128 threads) per batch element.
// pooled = [mean(128) | max(128)]; empty segments -> zeros.
// ---------------------------------------------------------------------------
__global__ void __launch_bounds__(128) head_kernel(
    const float* __restrict__ W1, const float* __restrict__ b1,   // [256,128],[128]
    const float* __restrict__ W2, const float* __restrict__ b2,   // [128, 64],[ 64]
    const float* __restrict__ W3, const float* __restrict__ b3,   // [ 64, 32],[ 32]
    const float* __restrict__ W4, const float* __restrict__ b4,   // [ 32,  4],[  4]
    float* __restrict__ out)                                      // [B, 4]
{
    const int b = blockIdx.x;
    const int t = threadIdx.x;

    __shared__ float pooled[2 * C_CH];
    __shared__ float h1[128];
    __shared__ float h2[64];
    __shared__ float h3[32];

    float cnt = g_cnt[b];
    bool  ne  = cnt > 0.0f;
    float sum = g_sum[b * C_CH + t];
    float mx  = k2f(g_maxk[b * C_CH + t]);
    pooled[t]        = ne ? (sum / cnt) : 0.0f;
    pooled[C_CH + t] = ne ? mx : 0.0f;
    __syncthreads();

    // Layer 1: [256] -> [128]
    {
        float acc = b1[t];
#pragma unroll 8
        for (int i = 0; i < 2 * C_CH; i++) acc += pooled[i] * W1[i * 128 + t];
        h1[t] = fmaxf(acc, 0.0f);
    }
    __syncthreads();

    // Layer 2: [128] -> [64]
    if (t < 64) {
        float acc = b2[t];
#pragma unroll 8
        for (int i = 0; i < 128; i++) acc += h1[i] * W2[i * 64 + t];
        h2[t] = fmaxf(acc, 0.0f);
    }
    __syncthreads();

    // Layer 3: [64] -> [32]
    if (t < 32) {
        float acc = b3[t];
#pragma unroll 8
        for (int i = 0; i < 64; i++) acc += h2[i] * W3[i * 32 + t];
        h3[t] = fmaxf(acc, 0.0f);
    }
    __syncthreads();

    // Layer 4: [32] -> [4]
    if (t < 4) {
        float acc = b4[t];
#pragma unroll
        for (int i = 0; i < 32; i++) acc += h3[i] * W4[i * 4 + t];
        out[b * 4 + t] = acc;
    }
}

// ---------------------------------------------------------------------------
extern "C" void kernel_launch(void* const* d_in, const int* in_sizes, int n_in,
                              void* d_out, int out_size)
{
    const float* feat = (const float*)d_in[0];
    const int*   bids = (const int*)d_in[1];

    // Inputs (metadata order): features, batch_ids, [batch_size scalar?],
    // W1,b1,W2,b2,W3,b3,W4,b4. Detect whether the scalar batch_size is present.
    int wbase = 2;
    if (n_in >= 11 && in_sizes[2] == 1) wbase = 3;  // skip scalar batch_size

    const float* W1 = (const float*)d_in[wbase + 0];
    const float* b1 = (const float*)d_in[wbase + 1];
    const float* W2 = (const float*)d_in[wbase + 2];
    const float* b2 = (const float*)d_in[wbase + 3];
    const float* W3 = (const float*)d_in[wbase + 4];
    const float* b3 = (const float*)d_in[wbase + 5];
    const float* W4 = (const float*)d_in[wbase + 6];
    const float* b4 = (const float*)d_in[wbase + 7];

    const int N = in_sizes[0] / C_CH;     // rows
    const int B = out_size / 4;           // batch size from output shape

    // 1) init scratch
    {
        int total   = B * C_CH;
        int threads = 256;
        int blocks  = (total + threads - 1) / threads;
        init_kernel<<<blocks, threads>>>(B);
    }

    // 2) segment reduce: 1184 blocks * 8 warps = 9472 warps
    {
        int blocks  = 1184;
        int threads = 256;
        int total_warps = blocks * (threads / 32);
        int rpw = (N + total_warps - 1) / total_warps;
        rpw = (rpw + 7) & ~7;   // multiple of 8 so the unrolled loop dominates
        reduce_kernel<<<blocks, threads>>>((const float4*)feat, bids, N, rpw);
    }

    // 3) finalize + MLP head
    head_kernel<<<B, 128>>>(W1, b1, W2, b2, W3, b3, W4, b4, (float*)d_out);
}